// round 5
// baseline (speedup 1.0000x reference)
#include <cuda_runtime.h>
#include <cuda_fp16.h>
#include <cstdint>

#define EDIM 64
#define NTH  512

// smem layout (bytes)
#define QH    0        // 128x128 fp16 Q hi                    32768
#define KH    32768    // 128x128 fp16 K hi                    32768
#define KL    65536    // 128x128 fp16 K lo                    32768
#define VH    98304    // 128x64  fp16 V hi                    16384
#define VL    114688   // 128x64  fp16 V lo                    16384
#define RAWK  131072   // 128x128 fp32 raw staging (reused as O-reduce buf)  65536
#define RAWV  196608   // 128x64  fp32 raw staging             32768
#define PMAX  229376   // 2x128 fp32                            1024
#define PSUM  230400   // 2x128 fp32                            1024
#define SMEM_BYTES 231424

__device__ __forceinline__ uint32_t smem_u32(const void* p) {
    uint32_t a;
    asm("{ .reg .u64 t; cvta.to.shared.u64 t, %1; cvt.u32.u64 %0, t; }" : "=r"(a) : "l"(p));
    return a;
}
__device__ __forceinline__ void ldsm4(uint32_t* r, uint32_t addr) {
    asm volatile("ldmatrix.sync.aligned.m8n8.x4.shared.b16 {%0,%1,%2,%3}, [%4];"
        : "=r"(r[0]), "=r"(r[1]), "=r"(r[2]), "=r"(r[3]) : "r"(addr));
}
__device__ __forceinline__ void ldsm4t(uint32_t* r, uint32_t addr) {
    asm volatile("ldmatrix.sync.aligned.m8n8.x4.trans.shared.b16 {%0,%1,%2,%3}, [%4];"
        : "=r"(r[0]), "=r"(r[1]), "=r"(r[2]), "=r"(r[3]) : "r"(addr));
}
__device__ __forceinline__ void mma16816(float* d, const uint32_t* a, uint32_t b0, uint32_t b1) {
    asm volatile("mma.sync.aligned.m16n8k16.row.col.f32.f16.f16.f32 "
        "{%0,%1,%2,%3}, {%4,%5,%6,%7}, {%8,%9}, {%0,%1,%2,%3};"
        : "+f"(d[0]), "+f"(d[1]), "+f"(d[2]), "+f"(d[3])
        : "r"(a[0]), "r"(a[1]), "r"(a[2]), "r"(a[3]), "r"(b0), "r"(b1));
}
#define CP_ASYNC16(dst, src) asm volatile("cp.async.cg.shared.global [%0], [%1], 16;" :: "r"(dst), "l"(src) : "memory")
#define CP_COMMIT()          asm volatile("cp.async.commit_group;" ::: "memory")
#define CP_WAIT0()           asm volatile("cp.async.wait_group 0;" ::: "memory")

__device__ __forceinline__ void cvt_splith(float4 v, uint2& hi, uint2& lo) {
    __half2 h0 = __floats2half2_rn(v.x, v.y);
    __half2 h1 = __floats2half2_rn(v.z, v.w);
    float rx = v.x - __half2float(__low2half(h0));
    float ry = v.y - __half2float(__high2half(h0));
    float rz = v.z - __half2float(__low2half(h1));
    float rw = v.w - __half2float(__high2half(h1));
    __half2 l0 = __floats2half2_rn(rx, ry);
    __half2 l1 = __floats2half2_rn(rz, rw);
    hi = make_uint2(*(uint32_t*)&h0, *(uint32_t*)&h1);
    lo = make_uint2(*(uint32_t*)&l0, *(uint32_t*)&l1);
}

__global__ __launch_bounds__(NTH, 1)
void local_attn_mma(const float* __restrict__ q,  const float* __restrict__ k,
                    const float* __restrict__ qr, const float* __restrict__ kr,
                    const float* __restrict__ v,  float* __restrict__ out, int T)
{
    extern __shared__ char sm[];
    const uint32_t sb = smem_u32(sm);
    const int tid  = threadIdx.x;
    const int wid  = tid >> 5;
    const int lane = tid & 31;
    const int wy   = wid & 7;     // row group: rows 16*wy .. 16*wy+15
    const int h    = wid >> 3;    // j-half: [64h, 64h+64)
    const int w    = blockIdx.x;
    const int b    = blockIdx.y;

    const long base  = (long)b * T * EDIM;
    const int  qrow0 = w * 128;

    const int nb  = (w == 0) ? 1 : 2;
    const int kb0 = w - nb + 1;

    // ---- prefetch raw K/V for first key block ----
    {
        const long kbase = base + (long)(kb0 * 128) * EDIM;
        #pragma unroll
        for (int it = 0; it < 8; ++it) {
            int idx = tid + it * NTH;                 // 0..4095
            int row = idx >> 5, c4 = idx & 31;
            const float* src = (c4 < 16) ? k : kr;
            CP_ASYNC16(sb + RAWK + idx * 16, src + kbase + (long)row * EDIM + (c4 & 15) * 4);
        }
        #pragma unroll
        for (int it = 0; it < 4; ++it) {
            int idx = tid + it * NTH;                 // 0..2047
            int row = idx >> 4, c4 = idx & 15;
            CP_ASYNC16(sb + RAWV + idx * 16, v + kbase + (long)row * EDIM + c4 * 4);
        }
        CP_COMMIT();
    }

    // ---- load Q [128][128] -> QH fp16 hi, swizzled ----
    #pragma unroll
    for (int it = 0; it < 8; ++it) {
        int idx = tid + it * NTH;
        int row = idx >> 5, f4 = idx & 31, f = f4 * 4;
        const float* src = (f < 64) ? q : qr;
        float4 val = *(const float4*)(src + base + (long)(qrow0 + row) * EDIM + (f & 63));
        __half2 h0 = __floats2half2_rn(val.x, val.y);
        __half2 h1 = __floats2half2_rn(val.z, val.w);
        uint2 hi = make_uint2(*(uint32_t*)&h0, *(uint32_t*)&h1);
        uint32_t off = (uint32_t)(row * 256 + (((f4 >> 1) ^ (row & 7)) << 4) + (f4 & 1) * 8);
        *(uint2*)(sm + QH + off) = hi;
    }

    const int mrow  = lane >> 2;
    const int cb    = (lane & 3) * 2;
    const int irow0 = wy * 16 + mrow;
    const int irow1 = irow0 + 8;
    const int tt    = lane >> 3, rr = lane & 7;

    float* pmax = (float*)(sm + PMAX);
    float* psum = (float*)(sm + PSUM);

    float mx0 = -1e30f, mx1 = -1e30f, l0 = 0.f, l1 = 0.f;
    float o[8][4];
    #pragma unroll
    for (int e = 0; e < 8; ++e) { o[e][0]=0.f; o[e][1]=0.f; o[e][2]=0.f; o[e][3]=0.f; }

    for (int ib = 0; ib < nb; ++ib) {
        CP_WAIT0();
        __syncthreads();

        // ---- convert raw fp32 -> fp16 hi/lo ----
        #pragma unroll
        for (int it = 0; it < 8; ++it) {
            int idx = tid + it * NTH;
            int row = idx >> 5, f4 = idx & 31;
            float4 val = *(const float4*)(sm + RAWK + idx * 16);
            uint2 hi, lo; cvt_splith(val, hi, lo);
            uint32_t off = (uint32_t)(row * 256 + (((f4 >> 1) ^ (row & 7)) << 4) + (f4 & 1) * 8);
            *(uint2*)(sm + KH + off) = hi;
            *(uint2*)(sm + KL + off) = lo;
        }
        #pragma unroll
        for (int it = 0; it < 4; ++it) {
            int idx = tid + it * NTH;
            int row = idx >> 4, f4 = idx & 15;
            float4 val = *(const float4*)(sm + RAWV + idx * 16);
            uint2 hi, lo; cvt_splith(val, hi, lo);
            uint32_t off = (uint32_t)(row * 128 + (((f4 >> 1) ^ (row & 7)) << 4) + (f4 & 1) * 8);
            *(uint2*)(sm + VH + off) = hi;
            *(uint2*)(sm + VL + off) = lo;
        }
        __syncthreads();

        // ---- prefetch next block (overlaps compute) ----
        if (ib + 1 < nb) {
            const long kbase = base + (long)((kb0 + ib + 1) * 128) * EDIM;
            #pragma unroll
            for (int it = 0; it < 8; ++it) {
                int idx = tid + it * NTH;
                int row = idx >> 5, c4 = idx & 31;
                const float* src = (c4 < 16) ? k : kr;
                CP_ASYNC16(sb + RAWK + idx * 16, src + kbase + (long)row * EDIM + (c4 & 15) * 4);
            }
            #pragma unroll
            for (int it = 0; it < 4; ++it) {
                int idx = tid + it * NTH;
                int row = idx >> 4, c4 = idx & 15;
                CP_ASYNC16(sb + RAWV + idx * 16, v + kbase + (long)row * EDIM + c4 * 4);
            }
            CP_COMMIT();
        }

        // ---- GEMM1: S[16 rows][64 j of half h], fp16 2-term ----
        float s[8][4];
        #pragma unroll
        for (int nt = 0; nt < 8; ++nt) { s[nt][0]=0.f; s[nt][1]=0.f; s[nt][2]=0.f; s[nt][3]=0.f; }

        #pragma unroll 1
        for (int kc = 0; kc < 8; ++kc) {
            int arow = wy * 16 + ((tt & 1) << 3) + rr;
            int ac16 = 2 * kc + (tt >> 1);
            uint32_t aoff = (uint32_t)(arow * 256 + ((ac16 ^ (arow & 7)) << 4));
            uint32_t ah[4];
            ldsm4(ah, sb + QH + aoff);
            #pragma unroll
            for (int np = 0; np < 4; ++np) {
                int brow = h * 64 + np * 16 + ((tt >> 1) << 3) + rr;
                int bc16 = 2 * kc + (tt & 1);
                uint32_t boff = (uint32_t)(brow * 256 + ((bc16 ^ (brow & 7)) << 4));
                uint32_t bh[4], bl[4];
                ldsm4(bh, sb + KH + boff);
                ldsm4(bl, sb + KL + boff);
                mma16816(s[2*np],   ah, bh[0], bh[1]);
                mma16816(s[2*np+1], ah, bh[2], bh[3]);
                mma16816(s[2*np],   ah, bl[0], bl[1]);
                mma16816(s[2*np+1], ah, bl[2], bl[3]);
            }
        }

        // ---- scale + mask + local row max ----
        const bool causal = (ib == nb - 1);
        float rm0 = -1e30f, rm1 = -1e30f;
        #pragma unroll
        for (int nt = 0; nt < 8; ++nt) {
            int c0 = h * 64 + nt * 8 + cb;
            #pragma unroll
            for (int cc = 0; cc < 2; ++cc) {
                float v0 = s[nt][cc]     * 0.125f;
                float v1 = s[nt][2 + cc] * 0.125f;
                if (causal && (c0 + cc > irow0)) v0 = -1e30f;
                if (causal && (c0 + cc > irow1)) v1 = -1e30f;
                s[nt][cc]     = v0;
                s[nt][2 + cc] = v1;
                rm0 = fmaxf(rm0, v0);
                rm1 = fmaxf(rm1, v1);
            }
        }
        rm0 = fmaxf(rm0, __shfl_xor_sync(0xffffffffu, rm0, 1));
        rm0 = fmaxf(rm0, __shfl_xor_sync(0xffffffffu, rm0, 2));
        rm1 = fmaxf(rm1, __shfl_xor_sync(0xffffffffu, rm1, 1));
        rm1 = fmaxf(rm1, __shfl_xor_sync(0xffffffffu, rm1, 2));

        // exchange per-half max
        pmax[h * 128 + irow0] = rm0;
        pmax[h * 128 + irow1] = rm1;
        __syncthreads();
        float gm0 = fmaxf(pmax[irow0], pmax[128 + irow0]);
        float gm1 = fmaxf(pmax[irow1], pmax[128 + irow1]);

        float mn0 = fmaxf(mx0, gm0), mn1 = fmaxf(mx1, gm1);
        float sf0 = __expf(mx0 - mn0), sf1 = __expf(mx1 - mn1);
        mx0 = mn0; mx1 = mn1;
        #pragma unroll
        for (int e = 0; e < 8; ++e) {
            o[e][0] *= sf0; o[e][1] *= sf0;
            o[e][2] *= sf1; o[e][3] *= sf1;
        }

        // ---- exp + pack P (fp16) + local sum ----
        uint32_t ph[16];
        float ls0 = 0.f, ls1 = 0.f;
        #pragma unroll
        for (int nt = 0; nt < 8; ++nt) {
            float p00 = __expf(s[nt][0] - mx0);
            float p01 = __expf(s[nt][1] - mx0);
            float p10 = __expf(s[nt][2] - mx1);
            float p11 = __expf(s[nt][3] - mx1);
            ls0 += p00 + p01;
            ls1 += p10 + p11;
            __half2 h0 = __floats2half2_rn(p00, p01);
            __half2 h1 = __floats2half2_rn(p10, p11);
            ph[2*nt]   = *(uint32_t*)&h0;
            ph[2*nt+1] = *(uint32_t*)&h1;
        }
        ls0 += __shfl_xor_sync(0xffffffffu, ls0, 1);
        ls0 += __shfl_xor_sync(0xffffffffu, ls0, 2);
        ls1 += __shfl_xor_sync(0xffffffffu, ls1, 1);
        ls1 += __shfl_xor_sync(0xffffffffu, ls1, 2);
        psum[h * 128 + irow0] = ls0;
        psum[h * 128 + irow1] = ls1;
        __syncthreads();
        l0 = l0 * sf0 + psum[irow0] + psum[128 + irow0];
        l1 = l1 * sf1 + psum[irow1] + psum[128 + irow1];

        // ---- GEMM2: O_partial += P * V (j in own half) ----
        #pragma unroll
        for (int jc = 0; jc < 4; ++jc) {
            const uint32_t* Ah = ph + 4 * jc;
            #pragma unroll
            for (int ep = 0; ep < 4; ++ep) {
                int vrow = h * 64 + jc * 16 + ((tt & 1) << 3) + rr;
                int vc16 = ep * 2 + (tt >> 1);
                uint32_t voff = (uint32_t)(vrow * 128 + ((vc16 ^ (vrow & 7)) << 4));
                uint32_t vh[4], vl[4];
                ldsm4t(vh, sb + VH + voff);
                ldsm4t(vl, sb + VL + voff);
                mma16816(o[2*ep],   Ah, vh[0], vh[1]);
                mma16816(o[2*ep+1], Ah, vh[2], vh[3]);
                mma16816(o[2*ep],   Ah, vl[0], vl[1]);
                mma16816(o[2*ep+1], Ah, vl[2], vl[3]);
            }
        }
    }

    // ---- cross-half O reduction (reuse RAWK as fp32 [128][64] buffer) ----
    float* ored = (float*)(sm + RAWK);
    __syncthreads();   // all warps done reading raw staging & smem phases
    if (h == 1) {
        #pragma unroll
        for (int e = 0; e < 8; ++e) {
            int col = e * 8 + cb;
            *(float2*)(ored + irow0 * 64 + col) = make_float2(o[e][0], o[e][1]);
            *(float2*)(ored + irow1 * 64 + col) = make_float2(o[e][2], o[e][3]);
        }
    }
    __syncthreads();
    if (h == 0) {
        float inv0 = 1.0f / l0, inv1 = 1.0f / l1;
        #pragma unroll
        for (int e = 0; e < 8; ++e) {
            int col = e * 8 + cb;
            float2 p0 = *(float2*)(ored + irow0 * 64 + col);
            float2 p1 = *(float2*)(ored + irow1 * 64 + col);
            *(float2*)(out + base + (long)(qrow0 + irow0) * EDIM + col) =
                make_float2((o[e][0] + p0.x) * inv0, (o[e][1] + p0.y) * inv0);
            *(float2*)(out + base + (long)(qrow0 + irow1) * EDIM + col) =
                make_float2((o[e][2] + p1.x) * inv1, (o[e][3] + p1.y) * inv1);
        }
    }
}

extern "C" void kernel_launch(void* const* d_in, const int* in_sizes, int n_in,
                              void* d_out, int out_size)
{
    const float* q  = (const float*)d_in[0];
    const float* k  = (const float*)d_in[1];
    const float* qr = (const float*)d_in[2];
    const float* kr = (const float*)d_in[3];
    const float* v  = (const float*)d_in[4];
    float* out      = (float*)d_out;

    const int T  = 4096;
    const int Bm = in_sizes[0] / (T * EDIM);
    const int W  = T / 128;

    cudaFuncSetAttribute(local_attn_mma, cudaFuncAttributeMaxDynamicSharedMemorySize, SMEM_BYTES);
    dim3 grid(W, Bm);
    local_attn_mma<<<grid, NTH, SMEM_BYTES>>>(q, k, qr, kr, v, out, T);
}

// round 6
// speedup vs baseline: 1.2347x; 1.2347x over previous
#include <cuda_runtime.h>
#include <cuda_fp16.h>
#include <cstdint>

#define EDIM 64
#define NTH  256

// smem (bytes): Q region is reused as KH after A-frags are cached in registers
#define KH 0        // phase 0: Q fp16 [128][128]; then K hi  (32768)
#define KL 32768    // K lo [128][128]                        (32768)
#define VH 65536    // V hi [128][64]                         (16384)
#define VL 81920    // V lo [128][64]                         (16384)
#define SMEM_BYTES 98304

__device__ __forceinline__ uint32_t smem_u32(const void* p) {
    uint32_t a;
    asm("{ .reg .u64 t; cvta.to.shared.u64 t, %1; cvt.u32.u64 %0, t; }" : "=r"(a) : "l"(p));
    return a;
}
__device__ __forceinline__ void ldsm4(uint32_t* r, uint32_t addr) {
    asm volatile("ldmatrix.sync.aligned.m8n8.x4.shared.b16 {%0,%1,%2,%3}, [%4];"
        : "=r"(r[0]), "=r"(r[1]), "=r"(r[2]), "=r"(r[3]) : "r"(addr));
}
__device__ __forceinline__ void ldsm4t(uint32_t* r, uint32_t addr) {
    asm volatile("ldmatrix.sync.aligned.m8n8.x4.trans.shared.b16 {%0,%1,%2,%3}, [%4];"
        : "=r"(r[0]), "=r"(r[1]), "=r"(r[2]), "=r"(r[3]) : "r"(addr));
}
__device__ __forceinline__ void mma16816(float* d, const uint32_t* a, uint32_t b0, uint32_t b1) {
    asm volatile("mma.sync.aligned.m16n8k16.row.col.f32.f16.f16.f32 "
        "{%0,%1,%2,%3}, {%4,%5,%6,%7}, {%8,%9}, {%0,%1,%2,%3};"
        : "+f"(d[0]), "+f"(d[1]), "+f"(d[2]), "+f"(d[3])
        : "r"(a[0]), "r"(a[1]), "r"(a[2]), "r"(a[3]), "r"(b0), "r"(b1));
}
__device__ __forceinline__ void cvt_splith(float4 v, uint2& hi, uint2& lo) {
    __half2 h0 = __floats2half2_rn(v.x, v.y);
    __half2 h1 = __floats2half2_rn(v.z, v.w);
    float rx = v.x - __half2float(__low2half(h0));
    float ry = v.y - __half2float(__high2half(h0));
    float rz = v.z - __half2float(__low2half(h1));
    float rw = v.w - __half2float(__high2half(h1));
    __half2 l0 = __floats2half2_rn(rx, ry);
    __half2 l1 = __floats2half2_rn(rz, rw);
    hi = make_uint2(*(uint32_t*)&h0, *(uint32_t*)&h1);
    lo = make_uint2(*(uint32_t*)&l0, *(uint32_t*)&l1);
}

__global__ __launch_bounds__(NTH, 2)
void local_attn_mma(const float* __restrict__ q,  const float* __restrict__ k,
                    const float* __restrict__ qr, const float* __restrict__ kr,
                    const float* __restrict__ v,  float* __restrict__ out, int T)
{
    extern __shared__ char sm[];
    const uint32_t sb = smem_u32(sm);
    const int tid  = threadIdx.x;
    const int wid  = tid >> 5;
    const int lane = tid & 31;
    const int w    = blockIdx.x;
    const int b    = blockIdx.y;

    const long base  = (long)b * T * EDIM;
    const int  qrow0 = w * 128;

    const int nb  = (w == 0) ? 1 : 2;
    const int kb0 = w - nb + 1;

    // ---- phase 0: Q fp32 -> fp16 into KH region ----
    #pragma unroll
    for (int it = 0; it < 16; ++it) {
        int idx = tid + it * NTH;
        int row = idx >> 5, f4 = idx & 31, f = f4 * 4;
        const float* src = (f < 64) ? q : qr;
        float4 val = *(const float4*)(src + base + (long)(qrow0 + row) * EDIM + (f & 63));
        __half2 h0 = __floats2half2_rn(val.x, val.y);
        __half2 h1 = __floats2half2_rn(val.z, val.w);
        uint2 hi = make_uint2(*(uint32_t*)&h0, *(uint32_t*)&h1);
        uint32_t off = (uint32_t)(row * 256 + (((f4 >> 1) ^ (row & 7)) << 4) + (f4 & 1) * 8);
        *(uint2*)(sm + KH + off) = hi;
    }
    __syncthreads();

    const int mrow  = lane >> 2;
    const int cb    = (lane & 3) * 2;
    const int irow0 = wid * 16 + mrow;
    const int irow1 = irow0 + 8;
    const int tt    = lane >> 3, rr = lane & 7;

    // ---- cache this warp's Q A-fragments (16 rows x 128 k) in 32 regs ----
    uint32_t qf[8][4];
    {
        int arow = wid * 16 + ((tt & 1) << 3) + rr;
        #pragma unroll
        for (int kc = 0; kc < 8; ++kc) {
            int ac16 = 2 * kc + (tt >> 1);
            uint32_t aoff = (uint32_t)(arow * 256 + ((ac16 ^ (arow & 7)) << 4));
            ldsm4(qf[kc], sb + KH + aoff);
        }
    }
    __syncthreads();   // all Q reads done before K overwrites the region

    float mx0 = -1e30f, mx1 = -1e30f, l0 = 0.f, l1 = 0.f;
    float o[8][4];
    #pragma unroll
    for (int e = 0; e < 8; ++e) { o[e][0]=0.f; o[e][1]=0.f; o[e][2]=0.f; o[e][3]=0.f; }

    for (int ib = 0; ib < nb; ++ib) {
        const long kbase = base + (long)((kb0 + ib) * 128) * EDIM;

        // ---- load+convert K [128][128] and V [128][64] ----
        #pragma unroll
        for (int it = 0; it < 16; ++it) {
            int idx = tid + it * NTH;
            int row = idx >> 5, f4 = idx & 31, f = f4 * 4;
            const float* src = (f < 64) ? k : kr;
            float4 val = *(const float4*)(src + kbase + (long)row * EDIM + (f & 63));
            uint2 hi, lo; cvt_splith(val, hi, lo);
            uint32_t off = (uint32_t)(row * 256 + (((f4 >> 1) ^ (row & 7)) << 4) + (f4 & 1) * 8);
            *(uint2*)(sm + KH + off) = hi;
            *(uint2*)(sm + KL + off) = lo;
        }
        #pragma unroll
        for (int it = 0; it < 8; ++it) {
            int idx = tid + it * NTH;
            int row = idx >> 4, f4 = idx & 15;
            float4 val = *(const float4*)(v + kbase + (long)row * EDIM + f4 * 4);
            uint2 hi, lo; cvt_splith(val, hi, lo);
            uint32_t off = (uint32_t)(row * 128 + (((f4 >> 1) ^ (row & 7)) << 4) + (f4 & 1) * 8);
            *(uint2*)(sm + VH + off) = hi;
            *(uint2*)(sm + VL + off) = lo;
        }
        __syncthreads();

        const bool causal = (ib == nb - 1);

        // ---- two 64-j chunks ----
        #pragma unroll 1
        for (int c = 0; c < 2; ++c) {
            const int jbase = c * 64;

            // GEMM1: S[16 rows][64 j], fp16 2-term
            float s[8][4];
            #pragma unroll
            for (int nt = 0; nt < 8; ++nt) { s[nt][0]=0.f; s[nt][1]=0.f; s[nt][2]=0.f; s[nt][3]=0.f; }

            #pragma unroll 1
            for (int kc = 0; kc < 8; ++kc) {
                #pragma unroll
                for (int np = 0; np < 4; ++np) {
                    int brow = jbase + np * 16 + ((tt >> 1) << 3) + rr;
                    int bc16 = 2 * kc + (tt & 1);
                    uint32_t boff = (uint32_t)(brow * 256 + ((bc16 ^ (brow & 7)) << 4));
                    uint32_t bh[4], bl[4];
                    ldsm4(bh, sb + KH + boff);
                    ldsm4(bl, sb + KL + boff);
                    mma16816(s[2*np],   qf[kc], bh[0], bh[1]);
                    mma16816(s[2*np+1], qf[kc], bh[2], bh[3]);
                    mma16816(s[2*np],   qf[kc], bl[0], bl[1]);
                    mma16816(s[2*np+1], qf[kc], bl[2], bl[3]);
                }
            }

            // scale + mask + warp-local row max
            float rm0 = -1e30f, rm1 = -1e30f;
            #pragma unroll
            for (int nt = 0; nt < 8; ++nt) {
                int c0 = jbase + nt * 8 + cb;
                #pragma unroll
                for (int cc = 0; cc < 2; ++cc) {
                    float v0 = s[nt][cc]     * 0.125f;
                    float v1 = s[nt][2 + cc] * 0.125f;
                    if (causal && (c0 + cc > irow0)) v0 = -1e30f;
                    if (causal && (c0 + cc > irow1)) v1 = -1e30f;
                    s[nt][cc]     = v0;
                    s[nt][2 + cc] = v1;
                    rm0 = fmaxf(rm0, v0);
                    rm1 = fmaxf(rm1, v1);
                }
            }
            rm0 = fmaxf(rm0, __shfl_xor_sync(0xffffffffu, rm0, 1));
            rm0 = fmaxf(rm0, __shfl_xor_sync(0xffffffffu, rm0, 2));
            rm1 = fmaxf(rm1, __shfl_xor_sync(0xffffffffu, rm1, 1));
            rm1 = fmaxf(rm1, __shfl_xor_sync(0xffffffffu, rm1, 2));

            float mn0 = fmaxf(mx0, rm0), mn1 = fmaxf(mx1, rm1);
            float sf0 = __expf(mx0 - mn0), sf1 = __expf(mx1 - mn1);
            mx0 = mn0; mx1 = mn1;
            l0 *= sf0; l1 *= sf1;
            #pragma unroll
            for (int e = 0; e < 8; ++e) {
                o[e][0] *= sf0; o[e][1] *= sf0;
                o[e][2] *= sf1; o[e][3] *= sf1;
            }

            // exp + pack P (fp16)
            uint32_t ph[16];
            #pragma unroll
            for (int nt = 0; nt < 8; ++nt) {
                float p00 = __expf(s[nt][0] - mx0);
                float p01 = __expf(s[nt][1] - mx0);
                float p10 = __expf(s[nt][2] - mx1);
                float p11 = __expf(s[nt][3] - mx1);
                l0 += p00 + p01;
                l1 += p10 + p11;
                __half2 h0 = __floats2half2_rn(p00, p01);
                __half2 h1 = __floats2half2_rn(p10, p11);
                ph[2*nt]   = *(uint32_t*)&h0;
                ph[2*nt+1] = *(uint32_t*)&h1;
            }

            // GEMM2: O += P * V, fp16 2-term
            #pragma unroll
            for (int jc = 0; jc < 4; ++jc) {
                const uint32_t* Ah = ph + 4 * jc;
                #pragma unroll
                for (int ep = 0; ep < 4; ++ep) {
                    int vrow = jbase + jc * 16 + ((tt & 1) << 3) + rr;
                    int vc16 = ep * 2 + (tt >> 1);
                    uint32_t voff = (uint32_t)(vrow * 128 + ((vc16 ^ (vrow & 7)) << 4));
                    uint32_t vh[4], vl[4];
                    ldsm4t(vh, sb + VH + voff);
                    ldsm4t(vl, sb + VL + voff);
                    mma16816(o[2*ep],   Ah, vh[0], vh[1]);
                    mma16816(o[2*ep+1], Ah, vh[2], vh[3]);
                    mma16816(o[2*ep],   Ah, vl[0], vl[1]);
                    mma16816(o[2*ep+1], Ah, vl[2], vl[3]);
                }
            }
        }

        if (ib + 1 < nb) __syncthreads();   // smem reads done before next block's stores
    }

    // ---- epilogue ----
    l0 += __shfl_xor_sync(0xffffffffu, l0, 1);
    l0 += __shfl_xor_sync(0xffffffffu, l0, 2);
    l1 += __shfl_xor_sync(0xffffffffu, l1, 1);
    l1 += __shfl_xor_sync(0xffffffffu, l1, 2);
    float inv0 = 1.0f / l0, inv1 = 1.0f / l1;
    #pragma unroll
    for (int e = 0; e < 8; ++e) {
        int col = e * 8 + cb;
        *(float2*)(out + base + (long)(qrow0 + irow0) * EDIM + col) =
            make_float2(o[e][0] * inv0, o[e][1] * inv0);
        *(float2*)(out + base + (long)(qrow0 + irow1) * EDIM + col) =
            make_float2(o[e][2] * inv1, o[e][3] * inv1);
    }
}

extern "C" void kernel_launch(void* const* d_in, const int* in_sizes, int n_in,
                              void* d_out, int out_size)
{
    const float* q  = (const float*)d_in[0];
    const float* k  = (const float*)d_in[1];
    const float* qr = (const float*)d_in[2];
    const float* kr = (const float*)d_in[3];
    const float* v  = (const float*)d_in[4];
    float* out      = (float*)d_out;

    const int T  = 4096;
    const int Bm = in_sizes[0] / (T * EDIM);
    const int W  = T / 128;

    cudaFuncSetAttribute(local_attn_mma, cudaFuncAttributeMaxDynamicSharedMemorySize, SMEM_BYTES);
    dim3 grid(W, Bm);
    local_attn_mma<<<grid, NTH, SMEM_BYTES>>>(q, k, qr, kr, v, out, T);
}

// round 7
// speedup vs baseline: 1.3683x; 1.1082x over previous
#include <cuda_runtime.h>
#include <cuda_fp16.h>
#include <cstdint>

#define EDIM 64
#define NTH  256

// smem (bytes): Q region reused as KH after A-frags cached in registers
#define KH 0        // phase 0: Q fp16 [128][128]; then K hi  (32768)
#define KL 32768    // K lo [128][128]                        (32768)
#define VH 65536    // V hi [128][64]                         (16384)
#define SMEM_BYTES 81920

__device__ __forceinline__ uint32_t smem_u32(const void* p) {
    uint32_t a;
    asm("{ .reg .u64 t; cvta.to.shared.u64 t, %1; cvt.u32.u64 %0, t; }" : "=r"(a) : "l"(p));
    return a;
}
__device__ __forceinline__ float ex2(float x) {
    float r;
    asm("ex2.approx.ftz.f32 %0, %1;" : "=f"(r) : "f"(x));
    return r;
}
__device__ __forceinline__ void ldsm4(uint32_t* r, uint32_t addr) {
    asm volatile("ldmatrix.sync.aligned.m8n8.x4.shared.b16 {%0,%1,%2,%3}, [%4];"
        : "=r"(r[0]), "=r"(r[1]), "=r"(r[2]), "=r"(r[3]) : "r"(addr));
}
__device__ __forceinline__ void ldsm4t(uint32_t* r, uint32_t addr) {
    asm volatile("ldmatrix.sync.aligned.m8n8.x4.trans.shared.b16 {%0,%1,%2,%3}, [%4];"
        : "=r"(r[0]), "=r"(r[1]), "=r"(r[2]), "=r"(r[3]) : "r"(addr));
}
__device__ __forceinline__ void mma16816(float* d, const uint32_t* a, uint32_t b0, uint32_t b1) {
    asm volatile("mma.sync.aligned.m16n8k16.row.col.f32.f16.f16.f32 "
        "{%0,%1,%2,%3}, {%4,%5,%6,%7}, {%8,%9}, {%0,%1,%2,%3};"
        : "+f"(d[0]), "+f"(d[1]), "+f"(d[2]), "+f"(d[3])
        : "r"(a[0]), "r"(a[1]), "r"(a[2]), "r"(a[3]), "r"(b0), "r"(b1));
}
__device__ __forceinline__ void cvt_splith(float4 v, uint2& hi, uint2& lo) {
    __half2 h0 = __floats2half2_rn(v.x, v.y);
    __half2 h1 = __floats2half2_rn(v.z, v.w);
    float rx = v.x - __half2float(__low2half(h0));
    float ry = v.y - __half2float(__high2half(h0));
    float rz = v.z - __half2float(__low2half(h1));
    float rw = v.w - __half2float(__high2half(h1));
    __half2 l0 = __floats2half2_rn(rx, ry);
    __half2 l1 = __floats2half2_rn(rz, rw);
    hi = make_uint2(*(uint32_t*)&h0, *(uint32_t*)&h1);
    lo = make_uint2(*(uint32_t*)&l0, *(uint32_t*)&l1);
}

__global__ __launch_bounds__(NTH, 2)
void local_attn_mma(const float* __restrict__ q,  const float* __restrict__ k,
                    const float* __restrict__ qr, const float* __restrict__ kr,
                    const float* __restrict__ v,  float* __restrict__ out, int T)
{
    extern __shared__ char sm[];
    const uint32_t sb = smem_u32(sm);
    const int tid  = threadIdx.x;
    const int wid  = tid >> 5;
    const int lane = tid & 31;
    const int w    = blockIdx.x;
    const int b    = blockIdx.y;

    const long base  = (long)b * T * EDIM;
    const int  qrow0 = w * 128;

    const int nb  = (w == 0) ? 1 : 2;
    const int kb0 = w - nb + 1;

    // logits computed directly in log2 domain: fold 0.125*log2(e) into Q
    const float QSCALE = 0.125f * 1.4426950408889634f;

    // ---- phase 0: Q (scaled) fp32 -> fp16 into KH region ----
    #pragma unroll
    for (int it = 0; it < 16; ++it) {
        int idx = tid + it * NTH;
        int row = idx >> 5, f4 = idx & 31, f = f4 * 4;
        const float* src = (f < 64) ? q : qr;
        float4 val = *(const float4*)(src + base + (long)(qrow0 + row) * EDIM + (f & 63));
        __half2 h0 = __floats2half2_rn(val.x * QSCALE, val.y * QSCALE);
        __half2 h1 = __floats2half2_rn(val.z * QSCALE, val.w * QSCALE);
        uint2 hi = make_uint2(*(uint32_t*)&h0, *(uint32_t*)&h1);
        uint32_t off = (uint32_t)(row * 256 + (((f4 >> 1) ^ (row & 7)) << 4) + (f4 & 1) * 8);
        *(uint2*)(sm + KH + off) = hi;
    }
    __syncthreads();

    const int mrow  = lane >> 2;
    const int cb    = (lane & 3) * 2;
    const int irow0 = wid * 16 + mrow;
    const int irow1 = irow0 + 8;
    const int tt    = lane >> 3, rr = lane & 7;

    // ---- cache this warp's Q A-fragments (16 rows x 128 k) in 32 regs ----
    uint32_t qf[8][4];
    {
        int arow = wid * 16 + ((tt & 1) << 3) + rr;
        #pragma unroll
        for (int kc = 0; kc < 8; ++kc) {
            int ac16 = 2 * kc + (tt >> 1);
            uint32_t aoff = (uint32_t)(arow * 256 + ((ac16 ^ (arow & 7)) << 4));
            ldsm4(qf[kc], sb + KH + aoff);
        }
    }
    __syncthreads();   // Q reads done before K overwrites the region

    float mx0 = -1e30f, mx1 = -1e30f, l0 = 0.f, l1 = 0.f;
    float o[8][4];
    #pragma unroll
    for (int e = 0; e < 8; ++e) { o[e][0]=0.f; o[e][1]=0.f; o[e][2]=0.f; o[e][3]=0.f; }

    for (int ib = 0; ib < nb; ++ib) {
        const long kbase = base + (long)((kb0 + ib) * 128) * EDIM;

        // ---- load+convert K [128][128] hi/lo and V [128][64] hi ----
        #pragma unroll
        for (int it = 0; it < 16; ++it) {
            int idx = tid + it * NTH;
            int row = idx >> 5, f4 = idx & 31, f = f4 * 4;
            const float* src = (f < 64) ? k : kr;
            float4 val = *(const float4*)(src + kbase + (long)row * EDIM + (f & 63));
            uint2 hi, lo; cvt_splith(val, hi, lo);
            uint32_t off = (uint32_t)(row * 256 + (((f4 >> 1) ^ (row & 7)) << 4) + (f4 & 1) * 8);
            *(uint2*)(sm + KH + off) = hi;
            *(uint2*)(sm + KL + off) = lo;
        }
        #pragma unroll
        for (int it = 0; it < 8; ++it) {
            int idx = tid + it * NTH;
            int row = idx >> 4, f4 = idx & 15;
            float4 val = *(const float4*)(v + kbase + (long)row * EDIM + f4 * 4);
            __half2 h0 = __floats2half2_rn(val.x, val.y);
            __half2 h1 = __floats2half2_rn(val.z, val.w);
            uint2 hi = make_uint2(*(uint32_t*)&h0, *(uint32_t*)&h1);
            uint32_t off = (uint32_t)(row * 128 + (((f4 >> 1) ^ (row & 7)) << 4) + (f4 & 1) * 8);
            *(uint2*)(sm + VH + off) = hi;
        }
        __syncthreads();

        const bool causal = (ib == nb - 1);

        // ---- two 64-j chunks ----
        #pragma unroll 1
        for (int c = 0; c < 2; ++c) {
            const int jbase = c * 64;

            // GEMM1: S[16 rows][64 j], fp16 2-term (qh*kh + qh*kl)
            float s[8][4];
            #pragma unroll
            for (int nt = 0; nt < 8; ++nt) { s[nt][0]=0.f; s[nt][1]=0.f; s[nt][2]=0.f; s[nt][3]=0.f; }

            #pragma unroll 1
            for (int kc = 0; kc < 8; ++kc) {
                #pragma unroll
                for (int np = 0; np < 4; ++np) {
                    int brow = jbase + np * 16 + ((tt >> 1) << 3) + rr;
                    int bc16 = 2 * kc + (tt & 1);
                    uint32_t boff = (uint32_t)(brow * 256 + ((bc16 ^ (brow & 7)) << 4));
                    uint32_t bh[4], bl[4];
                    ldsm4(bh, sb + KH + boff);
                    ldsm4(bl, sb + KL + boff);
                    mma16816(s[2*np],   qf[kc], bh[0], bh[1]);
                    mma16816(s[2*np+1], qf[kc], bh[2], bh[3]);
                    mma16816(s[2*np],   qf[kc], bl[0], bl[1]);
                    mma16816(s[2*np+1], qf[kc], bl[2], bl[3]);
                }
            }

            // mask + warp-local row max (logits already in log2 domain)
            float rm0 = -1e30f, rm1 = -1e30f;
            #pragma unroll
            for (int nt = 0; nt < 8; ++nt) {
                int c0 = jbase + nt * 8 + cb;
                #pragma unroll
                for (int cc = 0; cc < 2; ++cc) {
                    float v0 = s[nt][cc];
                    float v1 = s[nt][2 + cc];
                    if (causal && (c0 + cc > irow0)) v0 = -1e30f;
                    if (causal && (c0 + cc > irow1)) v1 = -1e30f;
                    s[nt][cc]     = v0;
                    s[nt][2 + cc] = v1;
                    rm0 = fmaxf(rm0, v0);
                    rm1 = fmaxf(rm1, v1);
                }
            }
            rm0 = fmaxf(rm0, __shfl_xor_sync(0xffffffffu, rm0, 1));
            rm0 = fmaxf(rm0, __shfl_xor_sync(0xffffffffu, rm0, 2));
            rm1 = fmaxf(rm1, __shfl_xor_sync(0xffffffffu, rm1, 1));
            rm1 = fmaxf(rm1, __shfl_xor_sync(0xffffffffu, rm1, 2));

            float mn0 = fmaxf(mx0, rm0), mn1 = fmaxf(mx1, rm1);
            float sf0 = ex2(mx0 - mn0), sf1 = ex2(mx1 - mn1);
            mx0 = mn0; mx1 = mn1;
            l0 *= sf0; l1 *= sf1;
            #pragma unroll
            for (int e = 0; e < 8; ++e) {
                o[e][0] *= sf0; o[e][1] *= sf0;
                o[e][2] *= sf1; o[e][3] *= sf1;
            }

            // exp2 + pack P (fp16)
            uint32_t ph[16];
            #pragma unroll
            for (int nt = 0; nt < 8; ++nt) {
                float p00 = ex2(s[nt][0] - mx0);
                float p01 = ex2(s[nt][1] - mx0);
                float p10 = ex2(s[nt][2] - mx1);
                float p11 = ex2(s[nt][3] - mx1);
                l0 += p00 + p01;
                l1 += p10 + p11;
                __half2 h0 = __floats2half2_rn(p00, p01);
                __half2 h1 = __floats2half2_rn(p10, p11);
                ph[2*nt]   = *(uint32_t*)&h0;
                ph[2*nt+1] = *(uint32_t*)&h1;
            }

            // GEMM2: O += P * V (single fp16 term)
            #pragma unroll
            for (int jc = 0; jc < 4; ++jc) {
                const uint32_t* Ah = ph + 4 * jc;
                #pragma unroll
                for (int ep = 0; ep < 4; ++ep) {
                    int vrow = jbase + jc * 16 + ((tt & 1) << 3) + rr;
                    int vc16 = ep * 2 + (tt >> 1);
                    uint32_t voff = (uint32_t)(vrow * 128 + ((vc16 ^ (vrow & 7)) << 4));
                    uint32_t vh[4];
                    ldsm4t(vh, sb + VH + voff);
                    mma16816(o[2*ep],   Ah, vh[0], vh[1]);
                    mma16816(o[2*ep+1], Ah, vh[2], vh[3]);
                }
            }
        }

        if (ib + 1 < nb) __syncthreads();
    }

    // ---- epilogue ----
    l0 += __shfl_xor_sync(0xffffffffu, l0, 1);
    l0 += __shfl_xor_sync(0xffffffffu, l0, 2);
    l1 += __shfl_xor_sync(0xffffffffu, l1, 1);
    l1 += __shfl_xor_sync(0xffffffffu, l1, 2);
    float inv0 = 1.0f / l0, inv1 = 1.0f / l1;
    #pragma unroll
    for (int e = 0; e < 8; ++e) {
        int col = e * 8 + cb;
        *(float2*)(out + base + (long)(qrow0 + irow0) * EDIM + col) =
            make_float2(o[e][0] * inv0, o[e][1] * inv0);
        *(float2*)(out + base + (long)(qrow0 + irow1) * EDIM + col) =
            make_float2(o[e][2] * inv1, o[e][3] * inv1);
    }
}

extern "C" void kernel_launch(void* const* d_in, const int* in_sizes, int n_in,
                              void* d_out, int out_size)
{
    const float* q  = (const float*)d_in[0];
    const float* k  = (const float*)d_in[1];
    const float* qr = (const float*)d_in[2];
    const float* kr = (const float*)d_in[3];
    const float* v  = (const float*)d_in[4];
    float* out      = (float*)d_out;

    const int T  = 4096;
    const int Bm = in_sizes[0] / (T * EDIM);
    const int W  = T / 128;

    cudaFuncSetAttribute(local_attn_mma, cudaFuncAttributeMaxDynamicSharedMemorySize, SMEM_BYTES);
    dim3 grid(W, Bm);
    local_attn_mma<<<grid, NTH, SMEM_BYTES>>>(q, k, qr, kr, v, out, T);
}

// round 8
// speedup vs baseline: 1.4292x; 1.0445x over previous
#include <cuda_runtime.h>
#include <cuda_fp16.h>
#include <cstdint>

#define EDIM 64
#define NTH  256

// smem (bytes)
#define QL 0        // Q lo fp16 [128][128], persistent       (32768)
#define KH 32768    // phase 0: Q hi; then K hi [128][128]    (32768)
#define VH 65536    // V hi [128][64]                         (16384)
#define SMEM_BYTES 81920

__device__ __forceinline__ uint32_t smem_u32(const void* p) {
    uint32_t a;
    asm("{ .reg .u64 t; cvta.to.shared.u64 t, %1; cvt.u32.u64 %0, t; }" : "=r"(a) : "l"(p));
    return a;
}
__device__ __forceinline__ float ex2(float x) {
    float r;
    asm("ex2.approx.ftz.f32 %0, %1;" : "=f"(r) : "f"(x));
    return r;
}
__device__ __forceinline__ void ldsm4(uint32_t* r, uint32_t addr) {
    asm volatile("ldmatrix.sync.aligned.m8n8.x4.shared.b16 {%0,%1,%2,%3}, [%4];"
        : "=r"(r[0]), "=r"(r[1]), "=r"(r[2]), "=r"(r[3]) : "r"(addr));
}
__device__ __forceinline__ void ldsm4t(uint32_t* r, uint32_t addr) {
    asm volatile("ldmatrix.sync.aligned.m8n8.x4.trans.shared.b16 {%0,%1,%2,%3}, [%4];"
        : "=r"(r[0]), "=r"(r[1]), "=r"(r[2]), "=r"(r[3]) : "r"(addr));
}
__device__ __forceinline__ void mma16816(float* d, const uint32_t* a, uint32_t b0, uint32_t b1) {
    asm volatile("mma.sync.aligned.m16n8k16.row.col.f32.f16.f16.f32 "
        "{%0,%1,%2,%3}, {%4,%5,%6,%7}, {%8,%9}, {%0,%1,%2,%3};"
        : "+f"(d[0]), "+f"(d[1]), "+f"(d[2]), "+f"(d[3])
        : "r"(a[0]), "r"(a[1]), "r"(a[2]), "r"(a[3]), "r"(b0), "r"(b1));
}

__global__ __launch_bounds__(NTH, 2)
void local_attn_mma(const float* __restrict__ q,  const float* __restrict__ k,
                    const float* __restrict__ qr, const float* __restrict__ kr,
                    const float* __restrict__ v,  float* __restrict__ out, int T)
{
    extern __shared__ char sm[];
    const uint32_t sb = smem_u32(sm);
    const int tid  = threadIdx.x;
    const int wid  = tid >> 5;
    const int lane = tid & 31;
    const int w    = blockIdx.x;
    const int b    = blockIdx.y;

    const long base  = (long)b * T * EDIM;
    const int  qrow0 = w * 128;

    const int nb  = (w == 0) ? 1 : 2;
    const int kb0 = w - nb + 1;

    // logits in log2 domain: fold 0.125*log2(e) into Q
    const float QSCALE = 0.125f * 1.4426950408889634f;

    // ---- phase 0: Q (scaled) fp32 -> fp16 hi (into KH) + lo residual (into QL) ----
    #pragma unroll
    for (int it = 0; it < 16; ++it) {
        int idx = tid + it * NTH;
        int row = idx >> 5, f4 = idx & 31, f = f4 * 4;
        const float* src = (f < 64) ? q : qr;
        float4 val = *(const float4*)(src + base + (long)(qrow0 + row) * EDIM + (f & 63));
        val.x *= QSCALE; val.y *= QSCALE; val.z *= QSCALE; val.w *= QSCALE;
        __half2 h0 = __floats2half2_rn(val.x, val.y);
        __half2 h1 = __floats2half2_rn(val.z, val.w);
        __half2 l0 = __floats2half2_rn(val.x - __half2float(__low2half(h0)),
                                       val.y - __half2float(__high2half(h0)));
        __half2 l1 = __floats2half2_rn(val.z - __half2float(__low2half(h1)),
                                       val.w - __half2float(__high2half(h1)));
        uint32_t off = (uint32_t)(row * 256 + (((f4 >> 1) ^ (row & 7)) << 4) + (f4 & 1) * 8);
        *(uint2*)(sm + KH + off) = make_uint2(*(uint32_t*)&h0, *(uint32_t*)&h1);
        *(uint2*)(sm + QL + off) = make_uint2(*(uint32_t*)&l0, *(uint32_t*)&l1);
    }
    __syncthreads();

    const int mrow  = lane >> 2;
    const int cb    = (lane & 3) * 2;
    const int irow0 = wid * 16 + mrow;
    const int irow1 = irow0 + 8;
    const int tt    = lane >> 3, rr = lane & 7;
    const int arow  = wid * 16 + ((tt & 1) << 3) + rr;

    // ---- cache this warp's Q-hi A-fragments in 32 regs ----
    uint32_t qf[8][4];
    #pragma unroll
    for (int kc = 0; kc < 8; ++kc) {
        int ac16 = 2 * kc + (tt >> 1);
        uint32_t aoff = (uint32_t)(arow * 256 + ((ac16 ^ (arow & 7)) << 4));
        ldsm4(qf[kc], sb + KH + aoff);
    }
    __syncthreads();   // Q-hi reads done before K overwrites KH

    float mx0 = -1e30f, mx1 = -1e30f, l0 = 0.f, l1 = 0.f;
    float o[8][4];
    #pragma unroll
    for (int e = 0; e < 8; ++e) { o[e][0]=0.f; o[e][1]=0.f; o[e][2]=0.f; o[e][3]=0.f; }

    for (int ib = 0; ib < nb; ++ib) {
        const long kbase = base + (long)((kb0 + ib) * 128) * EDIM;

        // ---- load+convert K hi [128][128] and V hi [128][64] ----
        #pragma unroll
        for (int it = 0; it < 16; ++it) {
            int idx = tid + it * NTH;
            int row = idx >> 5, f4 = idx & 31, f = f4 * 4;
            const float* src = (f < 64) ? k : kr;
            float4 val = *(const float4*)(src + kbase + (long)row * EDIM + (f & 63));
            __half2 h0 = __floats2half2_rn(val.x, val.y);
            __half2 h1 = __floats2half2_rn(val.z, val.w);
            uint32_t off = (uint32_t)(row * 256 + (((f4 >> 1) ^ (row & 7)) << 4) + (f4 & 1) * 8);
            *(uint2*)(sm + KH + off) = make_uint2(*(uint32_t*)&h0, *(uint32_t*)&h1);
        }
        #pragma unroll
        for (int it = 0; it < 8; ++it) {
            int idx = tid + it * NTH;
            int row = idx >> 4, f4 = idx & 15;
            float4 val = *(const float4*)(v + kbase + (long)row * EDIM + f4 * 4);
            __half2 h0 = __floats2half2_rn(val.x, val.y);
            __half2 h1 = __floats2half2_rn(val.z, val.w);
            uint32_t off = (uint32_t)(row * 128 + (((f4 >> 1) ^ (row & 7)) << 4) + (f4 & 1) * 8);
            *(uint2*)(sm + VH + off) = make_uint2(*(uint32_t*)&h0, *(uint32_t*)&h1);
        }
        __syncthreads();

        const bool causal = (ib == nb - 1);

        // ---- two 64-j chunks ----
        #pragma unroll 1
        for (int c = 0; c < 2; ++c) {
            const int jbase = c * 64;
            // fully-masked warp-chunk skip (causal block, chunk above all rows)
            if (causal && jbase > wid * 16 + 15) continue;

            // GEMM1: S[16 rows][64 j] = (qh + ql) * kh
            float s[8][4];
            #pragma unroll
            for (int nt = 0; nt < 8; ++nt) { s[nt][0]=0.f; s[nt][1]=0.f; s[nt][2]=0.f; s[nt][3]=0.f; }

            #pragma unroll 1
            for (int kc = 0; kc < 8; ++kc) {
                // Q-lo A-fragment for this kc (reused across np)
                uint32_t qlf[4];
                {
                    int ac16 = 2 * kc + (tt >> 1);
                    uint32_t aoff = (uint32_t)(arow * 256 + ((ac16 ^ (arow & 7)) << 4));
                    ldsm4(qlf, sb + QL + aoff);
                }
                #pragma unroll
                for (int np = 0; np < 4; ++np) {
                    int brow = jbase + np * 16 + ((tt >> 1) << 3) + rr;
                    int bc16 = 2 * kc + (tt & 1);
                    uint32_t boff = (uint32_t)(brow * 256 + ((bc16 ^ (brow & 7)) << 4));
                    uint32_t bh[4];
                    ldsm4(bh, sb + KH + boff);
                    mma16816(s[2*np],   qf[kc], bh[0], bh[1]);
                    mma16816(s[2*np+1], qf[kc], bh[2], bh[3]);
                    mma16816(s[2*np],   qlf,    bh[0], bh[1]);
                    mma16816(s[2*np+1], qlf,    bh[2], bh[3]);
                }
            }

            // mask + warp-local row max
            float rm0 = -1e30f, rm1 = -1e30f;
            #pragma unroll
            for (int nt = 0; nt < 8; ++nt) {
                int c0 = jbase + nt * 8 + cb;
                #pragma unroll
                for (int cc = 0; cc < 2; ++cc) {
                    float v0 = s[nt][cc];
                    float v1 = s[nt][2 + cc];
                    if (causal && (c0 + cc > irow0)) v0 = -1e30f;
                    if (causal && (c0 + cc > irow1)) v1 = -1e30f;
                    s[nt][cc]     = v0;
                    s[nt][2 + cc] = v1;
                    rm0 = fmaxf(rm0, v0);
                    rm1 = fmaxf(rm1, v1);
                }
            }
            rm0 = fmaxf(rm0, __shfl_xor_sync(0xffffffffu, rm0, 1));
            rm0 = fmaxf(rm0, __shfl_xor_sync(0xffffffffu, rm0, 2));
            rm1 = fmaxf(rm1, __shfl_xor_sync(0xffffffffu, rm1, 1));
            rm1 = fmaxf(rm1, __shfl_xor_sync(0xffffffffu, rm1, 2));

            float mn0 = fmaxf(mx0, rm0), mn1 = fmaxf(mx1, rm1);
            float sf0 = ex2(mx0 - mn0), sf1 = ex2(mx1 - mn1);
            mx0 = mn0; mx1 = mn1;
            l0 *= sf0; l1 *= sf1;
            #pragma unroll
            for (int e = 0; e < 8; ++e) {
                o[e][0] *= sf0; o[e][1] *= sf0;
                o[e][2] *= sf1; o[e][3] *= sf1;
            }

            // exp2 + pack P (fp16)
            uint32_t ph[16];
            #pragma unroll
            for (int nt = 0; nt < 8; ++nt) {
                float p00 = ex2(s[nt][0] - mx0);
                float p01 = ex2(s[nt][1] - mx0);
                float p10 = ex2(s[nt][2] - mx1);
                float p11 = ex2(s[nt][3] - mx1);
                l0 += p00 + p01;
                l1 += p10 + p11;
                __half2 h0 = __floats2half2_rn(p00, p01);
                __half2 h1 = __floats2half2_rn(p10, p11);
                ph[2*nt]   = *(uint32_t*)&h0;
                ph[2*nt+1] = *(uint32_t*)&h1;
            }

            // GEMM2: O += P * V (single fp16 term)
            #pragma unroll
            for (int jc = 0; jc < 4; ++jc) {
                const uint32_t* Ah = ph + 4 * jc;
                #pragma unroll
                for (int ep = 0; ep < 4; ++ep) {
                    int vrow = jbase + jc * 16 + ((tt & 1) << 3) + rr;
                    int vc16 = ep * 2 + (tt >> 1);
                    uint32_t voff = (uint32_t)(vrow * 128 + ((vc16 ^ (vrow & 7)) << 4));
                    uint32_t vh[4];
                    ldsm4t(vh, sb + VH + voff);
                    mma16816(o[2*ep],   Ah, vh[0], vh[1]);
                    mma16816(o[2*ep+1], Ah, vh[2], vh[3]);
                }
            }
        }

        if (ib + 1 < nb) __syncthreads();
    }

    // ---- epilogue ----
    l0 += __shfl_xor_sync(0xffffffffu, l0, 1);
    l0 += __shfl_xor_sync(0xffffffffu, l0, 2);
    l1 += __shfl_xor_sync(0xffffffffu, l1, 1);
    l1 += __shfl_xor_sync(0xffffffffu, l1, 2);
    float inv0 = 1.0f / l0, inv1 = 1.0f / l1;
    #pragma unroll
    for (int e = 0; e < 8; ++e) {
        int col = e * 8 + cb;
        *(float2*)(out + base + (long)(qrow0 + irow0) * EDIM + col) =
            make_float2(o[e][0] * inv0, o[e][1] * inv0);
        *(float2*)(out + base + (long)(qrow0 + irow1) * EDIM + col) =
            make_float2(o[e][2] * inv1, o[e][3] * inv1);
    }
}

extern "C" void kernel_launch(void* const* d_in, const int* in_sizes, int n_in,
                              void* d_out, int out_size)
{
    const float* q  = (const float*)d_in[0];
    const float* k  = (const float*)d_in[1];
    const float* qr = (const float*)d_in[2];
    const float* kr = (const float*)d_in[3];
    const float* v  = (const float*)d_in[4];
    float* out      = (float*)d_out;

    const int T  = 4096;
    const int Bm = in_sizes[0] / (T * EDIM);
    const int W  = T / 128;

    cudaFuncSetAttribute(local_attn_mma, cudaFuncAttributeMaxDynamicSharedMemorySize, SMEM_BYTES);
    dim3 grid(W, Bm);
    local_attn_mma<<<grid, NTH, SMEM_BYTES>>>(q, k, qr, kr, v, out, T);
}

// round 9
// speedup vs baseline: 1.5402x; 1.0777x over previous
#include <cuda_runtime.h>
#include <cuda_fp16.h>
#include <cstdint>

#define EDIM 64
#define NTH  256

// smem (bytes)
#define QL 0        // Q lo fp16 [128][128], persistent       (32768)
#define KH 32768    // phase 0: Q hi; then K hi [128][128]    (32768)
#define VH 65536    // V hi [128][64]                         (16384)
#define SMEM_BYTES 81920

__device__ __forceinline__ uint32_t smem_u32(const void* p) {
    uint32_t a;
    asm("{ .reg .u64 t; cvta.to.shared.u64 t, %1; cvt.u32.u64 %0, t; }" : "=r"(a) : "l"(p));
    return a;
}
__device__ __forceinline__ float ex2(float x) {
    float r;
    asm("ex2.approx.ftz.f32 %0, %1;" : "=f"(r) : "f"(x));
    return r;
}
__device__ __forceinline__ void ldsm4(uint32_t* r, uint32_t addr) {
    asm volatile("ldmatrix.sync.aligned.m8n8.x4.shared.b16 {%0,%1,%2,%3}, [%4];"
        : "=r"(r[0]), "=r"(r[1]), "=r"(r[2]), "=r"(r[3]) : "r"(addr));
}
__device__ __forceinline__ void ldsm4t(uint32_t* r, uint32_t addr) {
    asm volatile("ldmatrix.sync.aligned.m8n8.x4.trans.shared.b16 {%0,%1,%2,%3}, [%4];"
        : "=r"(r[0]), "=r"(r[1]), "=r"(r[2]), "=r"(r[3]) : "r"(addr));
}
__device__ __forceinline__ void mma16816(float* d, const uint32_t* a, uint32_t b0, uint32_t b1) {
    asm volatile("mma.sync.aligned.m16n8k16.row.col.f32.f16.f16.f32 "
        "{%0,%1,%2,%3}, {%4,%5,%6,%7}, {%8,%9}, {%0,%1,%2,%3};"
        : "+f"(d[0]), "+f"(d[1]), "+f"(d[2]), "+f"(d[3])
        : "r"(a[0]), "r"(a[1]), "r"(a[2]), "r"(a[3]), "r"(b0), "r"(b1));
}

__global__ __launch_bounds__(NTH, 2)
void local_attn_mma(const float* __restrict__ q,  const float* __restrict__ k,
                    const float* __restrict__ qr, const float* __restrict__ kr,
                    const float* __restrict__ v,  float* __restrict__ out, int T)
{
    extern __shared__ char sm[];
    const uint32_t sb = smem_u32(sm);
    const int tid  = threadIdx.x;
    const int wid  = tid >> 5;
    const int lane = tid & 31;
    const int w    = blockIdx.x;
    const int b    = blockIdx.y;

    const long base  = (long)b * T * EDIM;
    const int  qrow0 = w * 128;

    const int nb  = (w == 0) ? 1 : 2;
    const int kb0 = w - nb + 1;

    // logits in log2 domain: fold 0.125*log2(e) into Q
    const float QSCALE = 0.125f * 1.4426950408889634f;

    // ---- phase 0: Q (scaled) fp32 -> fp16 hi (into KH) + lo residual (into QL) ----
    #pragma unroll
    for (int it = 0; it < 16; ++it) {
        int idx = tid + it * NTH;
        int row = idx >> 5, f4 = idx & 31, f = f4 * 4;
        const float* src = (f < 64) ? q : qr;
        float4 val = *(const float4*)(src + base + (long)(qrow0 + row) * EDIM + (f & 63));
        val.x *= QSCALE; val.y *= QSCALE; val.z *= QSCALE; val.w *= QSCALE;
        __half2 h0 = __floats2half2_rn(val.x, val.y);
        __half2 h1 = __floats2half2_rn(val.z, val.w);
        __half2 l0 = __floats2half2_rn(val.x - __half2float(__low2half(h0)),
                                       val.y - __half2float(__high2half(h0)));
        __half2 l1 = __floats2half2_rn(val.z - __half2float(__low2half(h1)),
                                       val.w - __half2float(__high2half(h1)));
        uint32_t off = (uint32_t)(row * 256 + (((f4 >> 1) ^ (row & 7)) << 4) + (f4 & 1) * 8);
        *(uint2*)(sm + KH + off) = make_uint2(*(uint32_t*)&h0, *(uint32_t*)&h1);
        *(uint2*)(sm + QL + off) = make_uint2(*(uint32_t*)&l0, *(uint32_t*)&l1);
    }
    __syncthreads();

    const int mrow  = lane >> 2;
    const int cb    = (lane & 3) * 2;
    const int irow0 = wid * 16 + mrow;
    const int irow1 = irow0 + 8;
    const int tt    = lane >> 3, rr = lane & 7;
    const int arow  = wid * 16 + ((tt & 1) << 3) + rr;
    const uint32_t abase = (uint32_t)(arow * 256);

    // ---- cache this warp's Q-hi A-fragments in 32 regs ----
    uint32_t qf[8][4];
    #pragma unroll
    for (int kc = 0; kc < 8; ++kc) {
        int ac16 = 2 * kc + (tt >> 1);
        uint32_t aoff = abase + (uint32_t)((ac16 ^ (arow & 7)) << 4);
        ldsm4(qf[kc], sb + KH + aoff);
    }
    __syncthreads();   // Q-hi reads done before K overwrites KH

    float mx0 = -1e30f, mx1 = -1e30f, l0 = 0.f, l1 = 0.f;
    float o[8][4];
    #pragma unroll
    for (int e = 0; e < 8; ++e) { o[e][0]=0.f; o[e][1]=0.f; o[e][2]=0.f; o[e][3]=0.f; }

    bool first = true;

    for (int ib = 0; ib < nb; ++ib) {
        const long kbase = base + (long)((kb0 + ib) * 128) * EDIM;

        // ---- load+convert K hi [128][128] and V hi [128][64] ----
        #pragma unroll
        for (int it = 0; it < 16; ++it) {
            int idx = tid + it * NTH;
            int row = idx >> 5, f4 = idx & 31, f = f4 * 4;
            const float* src = (f < 64) ? k : kr;
            float4 val = *(const float4*)(src + kbase + (long)row * EDIM + (f & 63));
            __half2 h0 = __floats2half2_rn(val.x, val.y);
            __half2 h1 = __floats2half2_rn(val.z, val.w);
            uint32_t off = (uint32_t)(row * 256 + (((f4 >> 1) ^ (row & 7)) << 4) + (f4 & 1) * 8);
            *(uint2*)(sm + KH + off) = make_uint2(*(uint32_t*)&h0, *(uint32_t*)&h1);
        }
        #pragma unroll
        for (int it = 0; it < 8; ++it) {
            int idx = tid + it * NTH;
            int row = idx >> 4, f4 = idx & 15;
            float4 val = *(const float4*)(v + kbase + (long)row * EDIM + f4 * 4);
            __half2 h0 = __floats2half2_rn(val.x, val.y);
            __half2 h1 = __floats2half2_rn(val.z, val.w);
            uint32_t off = (uint32_t)(row * 128 + (((f4 >> 1) ^ (row & 7)) << 4) + (f4 & 1) * 8);
            *(uint2*)(sm + VH + off) = make_uint2(*(uint32_t*)&h0, *(uint32_t*)&h1);
        }
        __syncthreads();

        const bool causal = (ib == nb - 1);

        // ---- two 64-j chunks ----
        #pragma unroll 1
        for (int c = 0; c < 2; ++c) {
            const int jbase = c * 64;
            // fully-masked warp-chunk skip (causal block, chunk above all rows)
            if (causal && jbase > wid * 16 + 15) continue;
            // warp-uniform: does this chunk need per-element masking at all?
            const bool needmask = causal && (jbase + 63 > wid * 16);

            // GEMM1: S[16 rows][64 j] = (qh + ql) * kh
            float s[8][4];
            #pragma unroll
            for (int nt = 0; nt < 8; ++nt) { s[nt][0]=0.f; s[nt][1]=0.f; s[nt][2]=0.f; s[nt][3]=0.f; }

            #pragma unroll 2
            for (int kc = 0; kc < 8; ++kc) {
                // Q-lo A-fragment for this kc (reused across np)
                uint32_t qlf[4];
                {
                    int ac16 = 2 * kc + (tt >> 1);
                    uint32_t aoff = abase + (uint32_t)((ac16 ^ (arow & 7)) << 4);
                    ldsm4(qlf, sb + QL + aoff);
                }
                #pragma unroll
                for (int np = 0; np < 4; ++np) {
                    int brow = jbase + np * 16 + ((tt >> 1) << 3) + rr;
                    int bc16 = 2 * kc + (tt & 1);
                    uint32_t boff = (uint32_t)(brow * 256 + ((bc16 ^ (brow & 7)) << 4));
                    uint32_t bh[4];
                    ldsm4(bh, sb + KH + boff);
                    mma16816(s[2*np],   qf[kc], bh[0], bh[1]);
                    mma16816(s[2*np+1], qf[kc], bh[2], bh[3]);
                    mma16816(s[2*np],   qlf,    bh[0], bh[1]);
                    mma16816(s[2*np+1], qlf,    bh[2], bh[3]);
                }
            }

            // mask (only when needed) + warp-local row max
            float rm0 = -1e30f, rm1 = -1e30f;
            if (needmask) {
                #pragma unroll
                for (int nt = 0; nt < 8; ++nt) {
                    int c0 = jbase + nt * 8 + cb;
                    #pragma unroll
                    for (int cc = 0; cc < 2; ++cc) {
                        float v0 = s[nt][cc];
                        float v1 = s[nt][2 + cc];
                        if (c0 + cc > irow0) v0 = -1e30f;
                        if (c0 + cc > irow1) v1 = -1e30f;
                        s[nt][cc]     = v0;
                        s[nt][2 + cc] = v1;
                        rm0 = fmaxf(rm0, v0);
                        rm1 = fmaxf(rm1, v1);
                    }
                }
            } else {
                #pragma unroll
                for (int nt = 0; nt < 8; ++nt) {
                    rm0 = fmaxf(rm0, fmaxf(s[nt][0], s[nt][1]));
                    rm1 = fmaxf(rm1, fmaxf(s[nt][2], s[nt][3]));
                }
            }
            rm0 = fmaxf(rm0, __shfl_xor_sync(0xffffffffu, rm0, 1));
            rm0 = fmaxf(rm0, __shfl_xor_sync(0xffffffffu, rm0, 2));
            rm1 = fmaxf(rm1, __shfl_xor_sync(0xffffffffu, rm1, 1));
            rm1 = fmaxf(rm1, __shfl_xor_sync(0xffffffffu, rm1, 2));

            if (first) {
                mx0 = rm0; mx1 = rm1;
                first = false;
            } else {
                float mn0 = fmaxf(mx0, rm0), mn1 = fmaxf(mx1, rm1);
                float sf0 = ex2(mx0 - mn0), sf1 = ex2(mx1 - mn1);
                mx0 = mn0; mx1 = mn1;
                l0 *= sf0; l1 *= sf1;
                #pragma unroll
                for (int e = 0; e < 8; ++e) {
                    o[e][0] *= sf0; o[e][1] *= sf0;
                    o[e][2] *= sf1; o[e][3] *= sf1;
                }
            }

            // exp2 + pack P (fp16)
            uint32_t ph[16];
            #pragma unroll
            for (int nt = 0; nt < 8; ++nt) {
                float p00 = ex2(s[nt][0] - mx0);
                float p01 = ex2(s[nt][1] - mx0);
                float p10 = ex2(s[nt][2] - mx1);
                float p11 = ex2(s[nt][3] - mx1);
                l0 += p00 + p01;
                l1 += p10 + p11;
                __half2 h0 = __floats2half2_rn(p00, p01);
                __half2 h1 = __floats2half2_rn(p10, p11);
                ph[2*nt]   = *(uint32_t*)&h0;
                ph[2*nt+1] = *(uint32_t*)&h1;
            }

            // GEMM2: O += P * V (single fp16 term)
            #pragma unroll
            for (int jc = 0; jc < 4; ++jc) {
                const uint32_t* Ah = ph + 4 * jc;
                #pragma unroll
                for (int ep = 0; ep < 4; ++ep) {
                    int vrow = jbase + jc * 16 + ((tt & 1) << 3) + rr;
                    int vc16 = ep * 2 + (tt >> 1);
                    uint32_t voff = (uint32_t)(vrow * 128 + ((vc16 ^ (vrow & 7)) << 4));
                    uint32_t vh[4];
                    ldsm4t(vh, sb + VH + voff);
                    mma16816(o[2*ep],   Ah, vh[0], vh[1]);
                    mma16816(o[2*ep+1], Ah, vh[2], vh[3]);
                }
            }
        }

        if (ib + 1 < nb) __syncthreads();
    }

    // ---- epilogue ----
    l0 += __shfl_xor_sync(0xffffffffu, l0, 1);
    l0 += __shfl_xor_sync(0xffffffffu, l0, 2);
    l1 += __shfl_xor_sync(0xffffffffu, l1, 1);
    l1 += __shfl_xor_sync(0xffffffffu, l1, 2);
    float inv0 = 1.0f / l0, inv1 = 1.0f / l1;
    float* orow0 = out + base + (long)(qrow0 + irow0) * EDIM + cb;
    float* orow1 = out + base + (long)(qrow0 + irow1) * EDIM + cb;
    #pragma unroll
    for (int e = 0; e < 8; ++e) {
        *(float2*)(orow0 + e * 8) = make_float2(o[e][0] * inv0, o[e][1] * inv0);
        *(float2*)(orow1 + e * 8) = make_float2(o[e][2] * inv1, o[e][3] * inv1);
    }
}

extern "C" void kernel_launch(void* const* d_in, const int* in_sizes, int n_in,
                              void* d_out, int out_size)
{
    const float* q  = (const float*)d_in[0];
    const float* k  = (const float*)d_in[1];
    const float* qr = (const float*)d_in[2];
    const float* kr = (const float*)d_in[3];
    const float* v  = (const float*)d_in[4];
    float* out      = (float*)d_out;

    const int T  = 4096;
    const int Bm = in_sizes[0] / (T * EDIM);
    const int W  = T / 128;

    cudaFuncSetAttribute(local_attn_mma, cudaFuncAttributeMaxDynamicSharedMemorySize, SMEM_BYTES);
    dim3 grid(W, Bm);
    local_attn_mma<<<grid, NTH, SMEM_BYTES>>>(q, k, qr, kr, v, out, T);
}